// round 8
// baseline (speedup 1.0000x reference)
#include <cuda_runtime.h>
#include <cstddef>

// BilinearMixture: out[e,c] = sum_w (sum_d u[ui,d]*W[w,d]*v[vi,d]) * scalars[w,c]
//                           + u_bias[ui,c] + v_bias[vi,c]
// E=2e6, D=128, NUM_W=3, C=5.
//
// Persistent software-pipelined warps: each warp loops over batches of 4 edges
// (8 lanes/edge). Iteration k: issue feature+bias loads for batch k+1 (indices
// prefetched in iteration k-1), then compute batch k from the other register
// buffer. Double-buffered Feat registers via structural 2x unroll. W in shared.

#define D 128
#define NUM_W 3
#define NUM_C 5
#define THREADS 256
#define WARPS_PER_BLOCK 8
#define MAX_CTAS 296   // 148 SMs * 2 CTAs

struct Feat { float4 u[4]; float4 v[4]; };

__device__ __forceinline__ void issue_feat(
    Feat& f, const float4* __restrict__ uf, const float4* __restrict__ vf,
    int ui, int vi, int l)
{
    const float4* up = uf + (size_t)ui * (D / 4);
    const float4* vp = vf + (size_t)vi * (D / 4);
#pragma unroll
    for (int i = 0; i < 4; i++) {
        f.u[i] = __ldg(up + i * 8 + l);
        f.v[i] = __ldg(vp + i * 8 + l);
    }
}

__device__ __forceinline__ void compute_batch(
    const Feat& f, const float4* __restrict__ sW, int l,
    float s0, float s1, float s2, float ub, float vb,
    float* __restrict__ out, int e_cur, int E)
{
    float b0 = 0.f, b1 = 0.f, b2 = 0.f;
#pragma unroll
    for (int i = 0; i < 4; i++) {
        const float p0 = f.u[i].x * f.v[i].x;
        const float p1 = f.u[i].y * f.v[i].y;
        const float p2 = f.u[i].z * f.v[i].z;
        const float p3 = f.u[i].w * f.v[i].w;
        const float4 w0 = sW[0 * 32 + i * 8 + l];
        const float4 w1 = sW[1 * 32 + i * 8 + l];
        const float4 w2 = sW[2 * 32 + i * 8 + l];
        b0 = fmaf(p0, w0.x, fmaf(p1, w0.y, fmaf(p2, w0.z, fmaf(p3, w0.w, b0))));
        b1 = fmaf(p0, w1.x, fmaf(p1, w1.y, fmaf(p2, w1.z, fmaf(p3, w1.w, b1))));
        b2 = fmaf(p0, w2.x, fmaf(p1, w2.y, fmaf(p2, w2.z, fmaf(p3, w2.w, b2))));
    }
#pragma unroll
    for (int off = 4; off; off >>= 1) {
        b0 += __shfl_xor_sync(0xffffffffu, b0, off);
        b1 += __shfl_xor_sync(0xffffffffu, b1, off);
        b2 += __shfl_xor_sync(0xffffffffu, b2, off);
    }
    if (l < NUM_C && e_cur < E) {
        float o = fmaf(b0, s0, fmaf(b1, s1, b2 * s2));
        __stcs(out + (size_t)e_cur * NUM_C + l, o + ub + vb);
    }
}

// One pipeline iteration: fill NXT for batch bn, prefetch idx for bn+TW,
// compute CUR for batch b, rotate state. Breaks out when done.
#define PIPE_ITER(CUR, NXT)                                                   \
    {                                                                         \
        float ub_n = 0.f, vb_n = 0.f;                                         \
        if (bn < NB) {                                                        \
            issue_feat(NXT, uf, vf, ui_n, vi_n, l);                           \
            if (l < NUM_C && (bn * 4 + g) < E) {                              \
                ub_n = __ldg(u_bias + (size_t)ui_n * NUM_C + l);              \
                vb_n = __ldg(v_bias + (size_t)vi_n * NUM_C + l);              \
            }                                                                 \
        }                                                                     \
        const int bnn = bn + TW;                                              \
        const int e_nn = bnn * 4 + g;                                         \
        const bool v_nn = (bnn < NB) && (e_nn < E);                           \
        const int ui_nn = v_nn ? __ldg(u_idx + e_nn) : 0;                     \
        const int vi_nn = v_nn ? __ldg(v_idx + e_nn) : 0;                     \
        compute_batch(CUR, sW, l, s0, s1, s2, ub, vb, out, b * 4 + g, E);     \
        b = bn; bn = bnn;                                                     \
        ui_n = ui_nn; vi_n = vi_nn; ub = ub_n; vb = vb_n;                     \
        if (b >= NB) break;                                                   \
    }

__global__ __launch_bounds__(THREADS, 2)
void bilinear_mixture_kernel(
    const float* __restrict__ u_feats,
    const float* __restrict__ v_feats,
    const int*   __restrict__ u_idx,
    const int*   __restrict__ v_idx,
    const float* __restrict__ W,
    const float* __restrict__ scalars,
    const float* __restrict__ u_bias,
    const float* __restrict__ v_bias,
    float*       __restrict__ out,
    int E)
{
    __shared__ float4 sW[NUM_W * 32];   // 1.5 KB
    if (threadIdx.x < NUM_W * 32)
        sW[threadIdx.x] = reinterpret_cast<const float4*>(W)[threadIdx.x];
    __syncthreads();

    const int tid  = threadIdx.x;
    const int lane = tid & 31;
    const int l    = lane & 7;
    const int g    = lane >> 3;
    const int warp = tid >> 5;

    const float4* __restrict__ uf = reinterpret_cast<const float4*>(u_feats);
    const float4* __restrict__ vf = reinterpret_cast<const float4*>(v_feats);

    float s0 = 0.f, s1 = 0.f, s2 = 0.f;
    if (l < NUM_C) {
        s0 = __ldg(scalars + 0 * NUM_C + l);
        s1 = __ldg(scalars + 1 * NUM_C + l);
        s2 = __ldg(scalars + 2 * NUM_C + l);
    }

    const int TW = gridDim.x * WARPS_PER_BLOCK;       // total warps
    const int NB = (E + 3) >> 2;                      // total batches (4 edges each)
    int b = blockIdx.x * WARPS_PER_BLOCK + warp;      // this warp's first batch
    if (b >= NB) return;

    Feat fA, fB;

    // Prologue: batch b into fA; prefetch idx for bn.
    {
        const int e0 = b * 4 + g;
        const bool v0 = e0 < E;
        const int ui = v0 ? __ldg(u_idx + e0) : 0;
        const int vi = v0 ? __ldg(v_idx + e0) : 0;
        issue_feat(fA, uf, vf, ui, vi, l);
        // biases for batch b (deliberately after feature issue)
        if (l < NUM_C && v0) {
            // reuse names below via ub/vb
        }
        float ub0 = 0.f, vb0 = 0.f;
        if (l < NUM_C && v0) {
            ub0 = __ldg(u_bias + (size_t)ui * NUM_C + l);
            vb0 = __ldg(v_bias + (size_t)vi * NUM_C + l);
        }
        int bn = b + TW;
        const int en = bn * 4 + g;
        const bool vn = (bn < NB) && (en < E);
        int ui_n = vn ? __ldg(u_idx + en) : 0;
        int vi_n = vn ? __ldg(v_idx + en) : 0;
        float ub = ub0, vb = vb0;

        while (true) {
            PIPE_ITER(fA, fB)
            PIPE_ITER(fB, fA)
        }
    }
}

extern "C" void kernel_launch(void* const* d_in, const int* in_sizes, int n_in,
                              void* d_out, int out_size)
{
    const float* u_feats = (const float*)d_in[0];
    const float* v_feats = (const float*)d_in[1];
    const int*   u_idx   = (const int*)  d_in[2];
    const int*   v_idx   = (const int*)  d_in[3];
    const float* W       = (const float*)d_in[4];
    const float* scalars = (const float*)d_in[5];
    const float* u_bias  = (const float*)d_in[6];
    const float* v_bias  = (const float*)d_in[7];
    float* out = (float*)d_out;

    int E = in_sizes[2];  // u_idx element count
    int NB = (E + 3) >> 2;
    long long need = ((long long)NB + WARPS_PER_BLOCK - 1) / WARPS_PER_BLOCK;
    int blocks = (int)(need < MAX_CTAS ? need : MAX_CTAS);

    bilinear_mixture_kernel<<<blocks, THREADS>>>(
        u_feats, v_feats, u_idx, v_idx, W, scalars, u_bias, v_bias, out, E);
}

// round 9
// speedup vs baseline: 1.0797x; 1.0797x over previous
#include <cuda_runtime.h>
#include <cstddef>

// BilinearMixture: out[e,c] = sum_w (sum_d u[ui,d]*W[w,d]*v[vi,d]) * scalars[w,c]
//                           + u_bias[ui,c] + v_bias[vi,c]
// E=2e6, D=128, NUM_W=3, C=5.
//
// Persistent warps, 3-deep software pipeline, register headroom so ptxas
// cannot sink the gathers:
//   __launch_bounds__(384,1) -> ~170 regs/thread available, 12 warps/SM.
//   Iteration i: compute batch i (buffer f[i%3]), issue features+bias for
//   batch i+2 into f[(i+2)%3], refill that idx slot with batch i+5's indices.
//   Gathers get ~2 iterations (~550+ cyc) of cover before consumption.

#define D 128
#define NUM_W 3
#define NUM_C 5
#define THREADS 384
#define WARPS_PER_BLOCK 12
#define GRID_SM 148

struct Feat { float4 u[4]; float4 v[4]; };

__device__ __forceinline__ void issue_feat(
    Feat& f, const float4* __restrict__ uf, const float4* __restrict__ vf,
    int ui, int vi, int l)
{
    const float4* up = uf + (size_t)ui * (D / 4);
    const float4* vp = vf + (size_t)vi * (D / 4);
#pragma unroll
    for (int i = 0; i < 4; i++) {
        f.u[i] = __ldg(up + i * 8 + l);
        f.v[i] = __ldg(vp + i * 8 + l);
    }
}

__device__ __forceinline__ void compute_batch(
    const Feat& f, const float4* __restrict__ sW, int l,
    float s0, float s1, float s2, float ub, float vb,
    float* __restrict__ out, int e_cur, int E)
{
    float b0 = 0.f, b1 = 0.f, b2 = 0.f;
#pragma unroll
    for (int i = 0; i < 4; i++) {
        const float p0 = f.u[i].x * f.v[i].x;
        const float p1 = f.u[i].y * f.v[i].y;
        const float p2 = f.u[i].z * f.v[i].z;
        const float p3 = f.u[i].w * f.v[i].w;
        const float4 w0 = sW[0 * 32 + i * 8 + l];
        const float4 w1 = sW[1 * 32 + i * 8 + l];
        const float4 w2 = sW[2 * 32 + i * 8 + l];
        b0 = fmaf(p0, w0.x, fmaf(p1, w0.y, fmaf(p2, w0.z, fmaf(p3, w0.w, b0))));
        b1 = fmaf(p0, w1.x, fmaf(p1, w1.y, fmaf(p2, w1.z, fmaf(p3, w1.w, b1))));
        b2 = fmaf(p0, w2.x, fmaf(p1, w2.y, fmaf(p2, w2.z, fmaf(p3, w2.w, b2))));
    }
#pragma unroll
    for (int off = 4; off; off >>= 1) {
        b0 += __shfl_xor_sync(0xffffffffu, b0, off);
        b1 += __shfl_xor_sync(0xffffffffu, b1, off);
        b2 += __shfl_xor_sync(0xffffffffu, b2, off);
    }
    if (l < NUM_C && e_cur < E) {
        float o = fmaf(b0, s0, fmaf(b1, s1, b2 * s2));
        __stcs(out + (size_t)e_cur * NUM_C + l, o + ub + vb);
    }
}

// One pipeline position. FC: buffer for current batch bc. FN/UBN/VBN: slot for
// batch bc+2TW (issued here). IUN/IVN: idx slot holding bc+2TW's indices
// (consumed, then refilled with bc+5TW's indices).
#define PIPE(FC, FN, UBC, VBC, UBN, VBN, IUN, IVN)                           \
    {                                                                        \
        const int bis = bc + 2 * TW;                                         \
        if (bis < NB) {                                                      \
            issue_feat(FN, uf, vf, IUN, IVN, l);                             \
            if (l < NUM_C) {                                                 \
                UBN = __ldg(u_bias + (size_t)IUN * NUM_C + l);               \
                VBN = __ldg(v_bias + (size_t)IVN * NUM_C + l);               \
            }                                                                \
        }                                                                    \
        const int bld = bc + 5 * TW;                                         \
        const int eld = bld * 4 + g;                                         \
        const bool vld = (bld < NB) && (eld < E);                            \
        IUN = vld ? __ldg(u_idx + eld) : 0;                                  \
        IVN = vld ? __ldg(v_idx + eld) : 0;                                  \
        compute_batch(FC, sW, l, s0, s1, s2, UBC, VBC, out, bc * 4 + g, E);  \
        bc += TW;                                                            \
        if (bc >= NB) break;                                                 \
    }

__global__ __launch_bounds__(THREADS, 1)
void bilinear_mixture_kernel(
    const float* __restrict__ u_feats,
    const float* __restrict__ v_feats,
    const int*   __restrict__ u_idx,
    const int*   __restrict__ v_idx,
    const float* __restrict__ W,
    const float* __restrict__ scalars,
    const float* __restrict__ u_bias,
    const float* __restrict__ v_bias,
    float*       __restrict__ out,
    int E)
{
    __shared__ float4 sW[NUM_W * 32];   // 1.5 KB
    if (threadIdx.x < NUM_W * 32)
        sW[threadIdx.x] = reinterpret_cast<const float4*>(W)[threadIdx.x];
    __syncthreads();

    const int tid  = threadIdx.x;
    const int lane = tid & 31;
    const int l    = lane & 7;
    const int g    = lane >> 3;
    const int warp = tid >> 5;

    const float4* __restrict__ uf = reinterpret_cast<const float4*>(u_feats);
    const float4* __restrict__ vf = reinterpret_cast<const float4*>(v_feats);

    float s0 = 0.f, s1 = 0.f, s2 = 0.f;
    if (l < NUM_C) {
        s0 = __ldg(scalars + 0 * NUM_C + l);
        s1 = __ldg(scalars + 1 * NUM_C + l);
        s2 = __ldg(scalars + 2 * NUM_C + l);
    }

    const int TW = gridDim.x * WARPS_PER_BLOCK;   // total warps
    const int NB = (E + 3) >> 2;                  // batches of 4 edges
    int bc = blockIdx.x * WARPS_PER_BLOCK + warp; // current compute batch
    if (bc >= NB) return;

    Feat f0, f1, f2;
    float ub0 = 0.f, vb0 = 0.f, ub1 = 0.f, vb1 = 0.f, ub2 = 0.f, vb2 = 0.f;
    int i0u, i0v, i1u, i1v, i2u, i2v;

    // ---- Prologue ----
    {
        // batch bc -> f0
        const int e0 = bc * 4 + g;
        const bool v0 = e0 < E;
        const int ui = v0 ? __ldg(u_idx + e0) : 0;
        const int vi = v0 ? __ldg(v_idx + e0) : 0;
        issue_feat(f0, uf, vf, ui, vi, l);
        if (l < NUM_C) {
            ub0 = __ldg(u_bias + (size_t)ui * NUM_C + l);
            vb0 = __ldg(v_bias + (size_t)vi * NUM_C + l);
        }
        // batch bc+TW -> f1
        const int b1 = bc + TW;
        if (b1 < NB) {
            const int e1 = b1 * 4 + g;
            const bool v1 = e1 < E;
            const int ui1 = v1 ? __ldg(u_idx + e1) : 0;
            const int vi1 = v1 ? __ldg(v_idx + e1) : 0;
            issue_feat(f1, uf, vf, ui1, vi1, l);
            if (l < NUM_C) {
                ub1 = __ldg(u_bias + (size_t)ui1 * NUM_C + l);
                vb1 = __ldg(v_bias + (size_t)vi1 * NUM_C + l);
            }
        }
        // idx slots: bc+2TW -> slot2, bc+3TW -> slot0, bc+4TW -> slot1
        {
            const int b2 = bc + 2 * TW, e2 = b2 * 4 + g;
            const bool v2 = (b2 < NB) && (e2 < E);
            i2u = v2 ? __ldg(u_idx + e2) : 0;
            i2v = v2 ? __ldg(v_idx + e2) : 0;
            const int b3 = bc + 3 * TW, e3 = b3 * 4 + g;
            const bool v3 = (b3 < NB) && (e3 < E);
            i0u = v3 ? __ldg(u_idx + e3) : 0;
            i0v = v3 ? __ldg(v_idx + e3) : 0;
            const int b4 = bc + 4 * TW, e4 = b4 * 4 + g;
            const bool v4 = (b4 < NB) && (e4 < E);
            i1u = v4 ? __ldg(u_idx + e4) : 0;
            i1v = v4 ? __ldg(v_idx + e4) : 0;
        }
    }

    // ---- Steady state: 3-position modulo schedule ----
    while (true) {
        PIPE(f0, f2, ub0, vb0, ub2, vb2, i2u, i2v)
        PIPE(f1, f0, ub1, vb1, ub0, vb0, i0u, i0v)
        PIPE(f2, f1, ub2, vb2, ub1, vb1, i1u, i1v)
    }
}

extern "C" void kernel_launch(void* const* d_in, const int* in_sizes, int n_in,
                              void* d_out, int out_size)
{
    const float* u_feats = (const float*)d_in[0];
    const float* v_feats = (const float*)d_in[1];
    const int*   u_idx   = (const int*)  d_in[2];
    const int*   v_idx   = (const int*)  d_in[3];
    const float* W       = (const float*)d_in[4];
    const float* scalars = (const float*)d_in[5];
    const float* u_bias  = (const float*)d_in[6];
    const float* v_bias  = (const float*)d_in[7];
    float* out = (float*)d_out;

    int E = in_sizes[2];  // u_idx element count
    int NB = (E + 3) >> 2;
    long long need = ((long long)NB + WARPS_PER_BLOCK - 1) / WARPS_PER_BLOCK;
    int blocks = (int)(need < GRID_SM ? need : GRID_SM);

    bilinear_mixture_kernel<<<blocks, THREADS>>>(
        u_feats, v_feats, u_idx, v_idx, W, scalars, u_bias, v_bias, out, E);
}

// round 10
// speedup vs baseline: 1.2302x; 1.1394x over previous
#include <cuda_runtime.h>
#include <cuda_fp16.h>
#include <cstddef>

// BilinearMixture: out[e,c] = sum_w (sum_d u[ui,d]*W[w,d]*v[vi,d]) * scalars[w,c]
//                           + u_bias[ui,c] + v_bias[vi,c]
// E=2e6, D=128, NUM_W=3, C=5.
//
// Two-phase: (1) convert fp32 feature tables to fp16 scratch (51 MB, fully
// L2-resident), (2) R5-shaped gather kernel (8 lanes/edge, 2 quads/warp) with
// half-width feature loads: 4 wf/edge instead of 8 on the L1-wavefront
// roofline that governs this kernel.

#define D 128
#define NUM_W 3
#define NUM_C 5
#define NUM_USERS 100000
#define NUM_ITEMS 100000
#define THREADS 256
#define WARPS_PER_BLOCK (THREADS / 32)
#define EDGES_PER_WARP 8
#define EDGES_PER_BLOCK (WARPS_PER_BLOCK * EDGES_PER_WARP)  // 64

// fp16 feature tables: one row = 128 halves = 16 uint4.
#define ROW_U4 (D / 8)            // 16 uint4 per row
__device__ uint4 g_u16[(size_t)NUM_USERS * ROW_U4];
__device__ uint4 g_v16[(size_t)NUM_ITEMS * ROW_U4];

// ---------------- conversion kernel: fp32 -> fp16 ----------------
__global__ __launch_bounds__(256)
void convert_kernel(const float4* __restrict__ u_src,
                    const float4* __restrict__ v_src,
                    int n_u4_u, int n_u4_v)   // uint4 counts per table
{
    const int total = n_u4_u + n_u4_v;
    for (int idx = blockIdx.x * blockDim.x + threadIdx.x; idx < total;
         idx += gridDim.x * blockDim.x)
    {
        const bool isV = idx >= n_u4_u;
        const int j = isV ? idx - n_u4_u : idx;
        const float4* s = isV ? v_src : u_src;
        const float4 a = s[2 * j];
        const float4 b = s[2 * j + 1];
        __half2 h0 = __floats2half2_rn(a.x, a.y);
        __half2 h1 = __floats2half2_rn(a.z, a.w);
        __half2 h2 = __floats2half2_rn(b.x, b.y);
        __half2 h3 = __floats2half2_rn(b.z, b.w);
        uint4 o;
        o.x = *reinterpret_cast<unsigned*>(&h0);
        o.y = *reinterpret_cast<unsigned*>(&h1);
        o.z = *reinterpret_cast<unsigned*>(&h2);
        o.w = *reinterpret_cast<unsigned*>(&h3);
        (isV ? g_v16 : g_u16)[j] = o;
    }
}

// Unpack uint4 (8 halves) into 8 floats.
__device__ __forceinline__ void h8_to_f8(const uint4& r, float* f) {
    const __half2* h = reinterpret_cast<const __half2*>(&r);
#pragma unroll
    for (int k = 0; k < 4; k++) {
        float2 t = __half22float2(h[k]);
        f[2 * k]     = t.x;
        f[2 * k + 1] = t.y;
    }
}

// ---------------- main kernel ----------------
__global__ __launch_bounds__(THREADS, 2)
void bilinear_mixture_kernel(
    const int*   __restrict__ u_idx,
    const int*   __restrict__ v_idx,
    const float* __restrict__ W,
    const float* __restrict__ scalars,
    const float* __restrict__ u_bias,
    const float* __restrict__ v_bias,
    float*       __restrict__ out,
    int E)
{
    const int tid  = threadIdx.x;
    const int lane = tid & 31;
    const int l    = lane & 7;        // lane within edge-group (0..7)
    const int g    = lane >> 3;       // edge-group within warp (0..3)
    const int warp = tid >> 5;

    const int ebase = blockIdx.x * EDGES_PER_BLOCK + warp * EDGES_PER_WARP;
    const int e0 = ebase + g;       // quad A edge
    const int e1 = ebase + 4 + g;   // quad B edge
    const bool val0 = (e0 < E);
    const bool val1 = (e1 < E);

    const int ui0 = val0 ? u_idx[e0] : 0;
    const int vi0 = val0 ? v_idx[e0] : 0;
    const int ui1 = val1 ? u_idx[e1] : 0;
    const int vi1 = val1 ? v_idx[e1] : 0;

    const uint4* up0 = g_u16 + (size_t)ui0 * ROW_U4;
    const uint4* vp0 = g_v16 + (size_t)vi0 * ROW_U4;
    const uint4* up1 = g_u16 + (size_t)ui1 * ROW_U4;
    const uint4* vp1 = g_v16 + (size_t)vi1 * ROW_U4;

    // Lane l covers uint4 index i*8+l (i=0,1): each instruction's 8-lane group
    // reads one contiguous 128B line. 8 loads total (MLP 8, 4 wf/edge).
    uint4 ua[2], va[2], ub4[2], vb4[2];
#pragma unroll
    for (int i = 0; i < 2; i++) {
        ua[i]  = up0[i * 8 + l];
        va[i]  = vp0[i * 8 + l];
        ub4[i] = up1[i * 8 + l];
        vb4[i] = vp1[i * 8 + l];
    }

    // Per-class constants + bias gathers (overlap with outstanding loads).
    float s0 = 0.f, s1 = 0.f, s2 = 0.f;
    float ubias0 = 0.f, vbias0 = 0.f, ubias1 = 0.f, vbias1 = 0.f;
    if (l < NUM_C) {
        s0 = __ldg(scalars + 0 * NUM_C + l);
        s1 = __ldg(scalars + 1 * NUM_C + l);
        s2 = __ldg(scalars + 2 * NUM_C + l);
        ubias0 = __ldg(u_bias + (size_t)ui0 * NUM_C + l);
        vbias0 = __ldg(v_bias + (size_t)vi0 * NUM_C + l);
        ubias1 = __ldg(u_bias + (size_t)ui1 * NUM_C + l);
        vbias1 = __ldg(v_bias + (size_t)vi1 * NUM_C + l);
    }

    const float4* __restrict__ Wp = reinterpret_cast<const float4*>(W);

    float a0 = 0.f, a1 = 0.f, a2 = 0.f;   // quad A bases
    float c0 = 0.f, c1 = 0.f, c2 = 0.f;   // quad B bases
#pragma unroll
    for (int i = 0; i < 2; i++) {
        // Lane owns d in [(i*8+l)*8, +8): W float4 indices (i*8+l)*2, +1.
        const int wbase = (i * 8 + l) * 2;
        const float4 w0a = __ldg(Wp + 0 * 32 + wbase), w0b = __ldg(Wp + 0 * 32 + wbase + 1);
        const float4 w1a = __ldg(Wp + 1 * 32 + wbase), w1b = __ldg(Wp + 1 * 32 + wbase + 1);
        const float4 w2a = __ldg(Wp + 2 * 32 + wbase), w2b = __ldg(Wp + 2 * 32 + wbase + 1);
        const float wA[3][8] = {
            {w0a.x, w0a.y, w0a.z, w0a.w, w0b.x, w0b.y, w0b.z, w0b.w},
            {w1a.x, w1a.y, w1a.z, w1a.w, w1b.x, w1b.y, w1b.z, w1b.w},
            {w2a.x, w2a.y, w2a.z, w2a.w, w2b.x, w2b.y, w2b.z, w2b.w}};

        {
            float fu[8], fv[8];
            h8_to_f8(ua[i], fu);
            h8_to_f8(va[i], fv);
#pragma unroll
            for (int j = 0; j < 8; j++) {
                const float p = fu[j] * fv[j];
                a0 = fmaf(p, wA[0][j], a0);
                a1 = fmaf(p, wA[1][j], a1);
                a2 = fmaf(p, wA[2][j], a2);
            }
        }
        {
            float fu[8], fv[8];
            h8_to_f8(ub4[i], fu);
            h8_to_f8(vb4[i], fv);
#pragma unroll
            for (int j = 0; j < 8; j++) {
                const float p = fu[j] * fv[j];
                c0 = fmaf(p, wA[0][j], c0);
                c1 = fmaf(p, wA[1][j], c1);
                c2 = fmaf(p, wA[2][j], c2);
            }
        }
    }

    // Butterfly over the 8-lane group: 3 rounds x 6 values (2 quads).
#pragma unroll
    for (int off = 4; off; off >>= 1) {
        a0 += __shfl_xor_sync(0xffffffffu, a0, off);
        a1 += __shfl_xor_sync(0xffffffffu, a1, off);
        a2 += __shfl_xor_sync(0xffffffffu, a2, off);
        c0 += __shfl_xor_sync(0xffffffffu, c0, off);
        c1 += __shfl_xor_sync(0xffffffffu, c1, off);
        c2 += __shfl_xor_sync(0xffffffffu, c2, off);
    }

    if (l < NUM_C) {
        if (val0) {
            float o = fmaf(a0, s0, fmaf(a1, s1, a2 * s2));
            __stcs(out + (size_t)e0 * NUM_C + l, o + ubias0 + vbias0);
        }
        if (val1) {
            float o = fmaf(c0, s0, fmaf(c1, s1, c2 * s2));
            __stcs(out + (size_t)e1 * NUM_C + l, o + ubias1 + vbias1);
        }
    }
}

extern "C" void kernel_launch(void* const* d_in, const int* in_sizes, int n_in,
                              void* d_out, int out_size)
{
    const float* u_feats = (const float*)d_in[0];
    const float* v_feats = (const float*)d_in[1];
    const int*   u_idx   = (const int*)  d_in[2];
    const int*   v_idx   = (const int*)  d_in[3];
    const float* W       = (const float*)d_in[4];
    const float* scalars = (const float*)d_in[5];
    const float* u_bias  = (const float*)d_in[6];
    const float* v_bias  = (const float*)d_in[7];
    float* out = (float*)d_out;

    int E = in_sizes[2];  // u_idx element count

    // Phase 1: convert feature tables to fp16 scratch.
    const int n_u4_u = NUM_USERS * ROW_U4;   // 1.6M uint4
    const int n_u4_v = NUM_ITEMS * ROW_U4;
    convert_kernel<<<1184, 256>>>(
        reinterpret_cast<const float4*>(u_feats),
        reinterpret_cast<const float4*>(v_feats),
        n_u4_u, n_u4_v);

    // Phase 2: main gather kernel.
    int blocks = (E + EDGES_PER_BLOCK - 1) / EDGES_PER_BLOCK;
    bilinear_mixture_kernel<<<blocks, THREADS>>>(
        u_idx, v_idx, W, scalars, u_bias, v_bias, out, E);
}

// round 11
// speedup vs baseline: 1.4831x; 1.2056x over previous
#include <cuda_runtime.h>
#include <cuda_fp16.h>
#include <cstddef>

// BilinearMixture: out[e,c] = sum_w (sum_d u[ui,d]*W[w,d]*v[vi,d]) * scalars[w,c]
//                           + u_bias[ui,c] + v_bias[vi,c]
// E=2e6, D=128, NUM_W=3, C=5.
//
// Phase 1: convert u/v feature tables AND W to fp16 scratch (51 MB tables ->
// fully L2-resident; DRAM out of the picture).
// Phase 2: 8 lanes/edge, 4 edges/warp (R4 shape), fp16 loads:
//   - features: 2 uint4/lane/side -> 4 wf/edge
//   - W: fp16 row-major, lane l reads uint4 (i*8+l): consecutive lane
//     addresses, 4 groups broadcast -> 1 wf/instruction, 1.5 wf/edge
//   - low regs -> __launch_bounds__(256,4), occ ~42%

#define D 128
#define NUM_W 3
#define NUM_C 5
#define NUM_USERS 100000
#define NUM_ITEMS 100000
#define THREADS 256
#define WARPS_PER_BLOCK (THREADS / 32)
#define EDGES_PER_WARP 4
#define EDGES_PER_BLOCK (WARPS_PER_BLOCK * EDGES_PER_WARP)  // 32

#define ROW_U4 (D / 8)            // 16 uint4 per 128-half row
__device__ uint4 g_u16[(size_t)NUM_USERS * ROW_U4];
__device__ uint4 g_v16[(size_t)NUM_ITEMS * ROW_U4];
__device__ uint4 g_w16[NUM_W * ROW_U4];     // 48 uint4

// ---------------- conversion kernel: fp32 -> fp16 ----------------
__global__ __launch_bounds__(256)
void convert_kernel(const float4* __restrict__ u_src,
                    const float4* __restrict__ v_src,
                    const float4* __restrict__ w_src,
                    int n_u, int n_v, int n_w)   // uint4 counts
{
    const int total = n_u + n_v + n_w;
    for (int idx = blockIdx.x * blockDim.x + threadIdx.x; idx < total;
         idx += gridDim.x * blockDim.x)
    {
        const float4* s;
        uint4* dst;
        int j;
        if (idx < n_u)              { s = u_src; dst = g_u16; j = idx; }
        else if (idx < n_u + n_v)   { s = v_src; dst = g_v16; j = idx - n_u; }
        else                        { s = w_src; dst = g_w16; j = idx - n_u - n_v; }
        const float4 a = s[2 * j];
        const float4 b = s[2 * j + 1];
        __half2 h0 = __floats2half2_rn(a.x, a.y);
        __half2 h1 = __floats2half2_rn(a.z, a.w);
        __half2 h2 = __floats2half2_rn(b.x, b.y);
        __half2 h3 = __floats2half2_rn(b.z, b.w);
        uint4 o;
        o.x = *reinterpret_cast<unsigned*>(&h0);
        o.y = *reinterpret_cast<unsigned*>(&h1);
        o.z = *reinterpret_cast<unsigned*>(&h2);
        o.w = *reinterpret_cast<unsigned*>(&h3);
        dst[j] = o;
    }
}

// Unpack uint4 (8 halves) into 8 floats.
__device__ __forceinline__ void h8_to_f8(const uint4& r, float* f) {
    const __half2* h = reinterpret_cast<const __half2*>(&r);
#pragma unroll
    for (int k = 0; k < 4; k++) {
        float2 t = __half22float2(h[k]);
        f[2 * k]     = t.x;
        f[2 * k + 1] = t.y;
    }
}

// ---------------- main kernel ----------------
__global__ __launch_bounds__(THREADS, 4)
void bilinear_mixture_kernel(
    const int*   __restrict__ u_idx,
    const int*   __restrict__ v_idx,
    const float* __restrict__ scalars,
    const float* __restrict__ u_bias,
    const float* __restrict__ v_bias,
    float*       __restrict__ out,
    int E)
{
    const int tid  = threadIdx.x;
    const int lane = tid & 31;
    const int l    = lane & 7;        // lane within edge-group (0..7)
    const int g    = lane >> 3;       // edge-group within warp (0..3)
    const int warp = tid >> 5;

    const int e = blockIdx.x * EDGES_PER_BLOCK + warp * EDGES_PER_WARP + g;
    if (e >= E) return;

    const int ui = u_idx[e];
    const int vi = v_idx[e];

    // Feature loads: lane l reads uint4 index i*8+l of each 16-uint4 row.
    // Each instruction: 4 groups x 1 line (128B) = 4 wf. MLP 4/lane.
    const uint4* up = g_u16 + (size_t)ui * ROW_U4;
    const uint4* vp = g_v16 + (size_t)vi * ROW_U4;
    uint4 ua[2], va[2];
#pragma unroll
    for (int i = 0; i < 2; i++) {
        ua[i] = up[i * 8 + l];
        va[i] = vp[i * 8 + l];
    }

    // Per-class constants + bias gathers (overlap with outstanding loads).
    float s0 = 0.f, s1 = 0.f, s2 = 0.f, ub = 0.f, vb = 0.f;
    if (l < NUM_C) {
        s0 = __ldg(scalars + 0 * NUM_C + l);
        s1 = __ldg(scalars + 1 * NUM_C + l);
        s2 = __ldg(scalars + 2 * NUM_C + l);
        ub = __ldg(u_bias + (size_t)ui * NUM_C + l);
        vb = __ldg(v_bias + (size_t)vi * NUM_C + l);
    }

    float b0 = 0.f, b1 = 0.f, b2 = 0.f;
#pragma unroll
    for (int i = 0; i < 2; i++) {
        // W fp16 loads: lanes 0..7 read consecutive uint4 -> one 128B line,
        // 4 groups broadcast -> 1 wf per instruction.
        const uint4 w0 = g_w16[0 * ROW_U4 + i * 8 + l];
        const uint4 w1 = g_w16[1 * ROW_U4 + i * 8 + l];
        const uint4 w2 = g_w16[2 * ROW_U4 + i * 8 + l];

        float fu[8], fv[8], fw0[8], fw1[8], fw2[8];
        h8_to_f8(ua[i], fu);
        h8_to_f8(va[i], fv);
        h8_to_f8(w0, fw0);
        h8_to_f8(w1, fw1);
        h8_to_f8(w2, fw2);
#pragma unroll
        for (int j = 0; j < 8; j++) {
            const float p = fu[j] * fv[j];
            b0 = fmaf(p, fw0[j], b0);
            b1 = fmaf(p, fw1[j], b1);
            b2 = fmaf(p, fw2[j], b2);
        }
    }

    // Butterfly over the 8-lane group: 3 rounds x 3 values.
#pragma unroll
    for (int off = 4; off; off >>= 1) {
        b0 += __shfl_xor_sync(0xffffffffu, b0, off);
        b1 += __shfl_xor_sync(0xffffffffu, b1, off);
        b2 += __shfl_xor_sync(0xffffffffu, b2, off);
    }

    if (l < NUM_C) {
        float o = fmaf(b0, s0, fmaf(b1, s1, b2 * s2));
        __stcs(out + (size_t)e * NUM_C + l, o + ub + vb);
    }
}

extern "C" void kernel_launch(void* const* d_in, const int* in_sizes, int n_in,
                              void* d_out, int out_size)
{
    const float* u_feats = (const float*)d_in[0];
    const float* v_feats = (const float*)d_in[1];
    const int*   u_idx   = (const int*)  d_in[2];
    const int*   v_idx   = (const int*)  d_in[3];
    const float* W       = (const float*)d_in[4];
    const float* scalars = (const float*)d_in[5];
    const float* u_bias  = (const float*)d_in[6];
    const float* v_bias  = (const float*)d_in[7];
    float* out = (float*)d_out;

    int E = in_sizes[2];  // u_idx element count

    // Phase 1: convert feature tables + W to fp16 scratch.
    const int n_u = NUM_USERS * ROW_U4;
    const int n_v = NUM_ITEMS * ROW_U4;
    const int n_w = NUM_W * ROW_U4;
    convert_kernel<<<1184, 256>>>(
        reinterpret_cast<const float4*>(u_feats),
        reinterpret_cast<const float4*>(v_feats),
        reinterpret_cast<const float4*>(W),
        n_u, n_v, n_w);

    // Phase 2: main gather kernel.
    int blocks = (E + EDGES_PER_BLOCK - 1) / EDGES_PER_BLOCK;
    bilinear_mixture_kernel<<<blocks, THREADS>>>(
        u_idx, v_idx, scalars, u_bias, v_bias, out, E);
}

// round 12
// speedup vs baseline: 1.7883x; 1.2058x over previous
#include <cuda_runtime.h>
#include <cuda_fp16.h>
#include <cstddef>

// BilinearMixture: out[e,c] = sum_w (sum_d u[ui,d]*W[w,d]*v[vi,d]) * scalars[w,c]
//                           + u_bias[ui,c] + v_bias[vi,c]
// E=2e6, D=128, NUM_W=3, C=5.
//
// Phase 1: convert u/v tables + W to fp16 scratch (51 MB -> L2-resident).
// Phase 2: 8 lanes/edge, 4 groups, 2 edges/thread (8 edges/warp):
//   - features: 4 wf/edge (2 uint4/lane/side)
//   - u*v via HMUL2 then cvt (saves 16 cvt+8 mul per edge vs unpack-both)
//   - W fp16 loaded+unpacked once per iter, shared by both edges (12 cvt/edge)
//   - ~96 math ops/edge vs 145 in prior round (issue/fma co-bound fix)

#define D 128
#define NUM_W 3
#define NUM_C 5
#define NUM_USERS 100000
#define NUM_ITEMS 100000
#define THREADS 256
#define WARPS_PER_BLOCK (THREADS / 32)
#define EDGES_PER_WARP 8
#define EDGES_PER_BLOCK (WARPS_PER_BLOCK * EDGES_PER_WARP)  // 64

#define ROW_U4 (D / 8)            // 16 uint4 per 128-half row
__device__ uint4 g_u16[(size_t)NUM_USERS * ROW_U4];
__device__ uint4 g_v16[(size_t)NUM_ITEMS * ROW_U4];
__device__ uint4 g_w16[NUM_W * ROW_U4];     // 48 uint4

// ---------------- conversion kernel: fp32 -> fp16 ----------------
__global__ __launch_bounds__(256)
void convert_kernel(const float4* __restrict__ u_src,
                    const float4* __restrict__ v_src,
                    const float4* __restrict__ w_src,
                    int n_u, int n_v, int n_w)   // uint4 counts
{
    const int total = n_u + n_v + n_w;
    for (int idx = blockIdx.x * blockDim.x + threadIdx.x; idx < total;
         idx += gridDim.x * blockDim.x)
    {
        const float4* s;
        uint4* dst;
        int j;
        if (idx < n_u)              { s = u_src; dst = g_u16; j = idx; }
        else if (idx < n_u + n_v)   { s = v_src; dst = g_v16; j = idx - n_u; }
        else                        { s = w_src; dst = g_w16; j = idx - n_u - n_v; }
        const float4 a = s[2 * j];
        const float4 b = s[2 * j + 1];
        __half2 h0 = __floats2half2_rn(a.x, a.y);
        __half2 h1 = __floats2half2_rn(a.z, a.w);
        __half2 h2 = __floats2half2_rn(b.x, b.y);
        __half2 h3 = __floats2half2_rn(b.z, b.w);
        uint4 o;
        o.x = *reinterpret_cast<unsigned*>(&h0);
        o.y = *reinterpret_cast<unsigned*>(&h1);
        o.z = *reinterpret_cast<unsigned*>(&h2);
        o.w = *reinterpret_cast<unsigned*>(&h3);
        dst[j] = o;
    }
}

// Unpack uint4 (8 halves) into 8 floats.
__device__ __forceinline__ void h8_to_f8(const uint4& r, float* f) {
    const __half2* h = reinterpret_cast<const __half2*>(&r);
#pragma unroll
    for (int k = 0; k < 4; k++) {
        float2 t = __half22float2(h[k]);
        f[2 * k]     = t.x;
        f[2 * k + 1] = t.y;
    }
}

// p = u ⊙ v computed in half2, then widened: 4 HMUL2 + 8 cvt.
__device__ __forceinline__ void hprod_to_f8(const uint4& u, const uint4& v, float* p) {
    const __half2* uh = reinterpret_cast<const __half2*>(&u);
    const __half2* vh = reinterpret_cast<const __half2*>(&v);
#pragma unroll
    for (int k = 0; k < 4; k++) {
        __half2 q = __hmul2(uh[k], vh[k]);
        float2 t = __half22float2(q);
        p[2 * k]     = t.x;
        p[2 * k + 1] = t.y;
    }
}

// ---------------- main kernel ----------------
__global__ __launch_bounds__(THREADS, 3)
void bilinear_mixture_kernel(
    const int*   __restrict__ u_idx,
    const int*   __restrict__ v_idx,
    const float* __restrict__ scalars,
    const float* __restrict__ u_bias,
    const float* __restrict__ v_bias,
    float*       __restrict__ out,
    int E)
{
    const int tid  = threadIdx.x;
    const int lane = tid & 31;
    const int l    = lane & 7;        // lane within edge-group (0..7)
    const int g    = lane >> 3;       // edge-group within warp (0..3)
    const int warp = tid >> 5;

    const int ebase = blockIdx.x * EDGES_PER_BLOCK + warp * EDGES_PER_WARP;
    const int e0 = ebase + g;       // quad A edge
    const int e1 = ebase + 4 + g;   // quad B edge
    const bool val0 = (e0 < E);
    const bool val1 = (e1 < E);

    const int ui0 = val0 ? u_idx[e0] : 0;
    const int vi0 = val0 ? v_idx[e0] : 0;
    const int ui1 = val1 ? u_idx[e1] : 0;
    const int vi1 = val1 ? v_idx[e1] : 0;

    const uint4* up0 = g_u16 + (size_t)ui0 * ROW_U4;
    const uint4* vp0 = g_v16 + (size_t)vi0 * ROW_U4;
    const uint4* up1 = g_u16 + (size_t)ui1 * ROW_U4;
    const uint4* vp1 = g_v16 + (size_t)vi1 * ROW_U4;

    // All 8 feature loads issued up front (MLP 8/lane, 4 wf/edge).
    uint4 ua[2], va[2], ub4[2], vb4[2];
#pragma unroll
    for (int i = 0; i < 2; i++) {
        ua[i]  = up0[i * 8 + l];
        va[i]  = vp0[i * 8 + l];
        ub4[i] = up1[i * 8 + l];
        vb4[i] = vp1[i * 8 + l];
    }

    // Per-class constants + bias gathers (overlap with outstanding loads).
    float s0 = 0.f, s1 = 0.f, s2 = 0.f;
    float ubias0 = 0.f, vbias0 = 0.f, ubias1 = 0.f, vbias1 = 0.f;
    if (l < NUM_C) {
        s0 = __ldg(scalars + 0 * NUM_C + l);
        s1 = __ldg(scalars + 1 * NUM_C + l);
        s2 = __ldg(scalars + 2 * NUM_C + l);
        ubias0 = __ldg(u_bias + (size_t)ui0 * NUM_C + l);
        vbias0 = __ldg(v_bias + (size_t)vi0 * NUM_C + l);
        ubias1 = __ldg(u_bias + (size_t)ui1 * NUM_C + l);
        vbias1 = __ldg(v_bias + (size_t)vi1 * NUM_C + l);
    }

    float a0 = 0.f, a1 = 0.f, a2 = 0.f;   // quad A bases
    float c0 = 0.f, c1 = 0.f, c2 = 0.f;   // quad B bases
#pragma unroll
    for (int i = 0; i < 2; i++) {
        // W fp16 broadcast loads (1 wf each), unpacked ONCE, shared by both edges.
        const uint4 w0 = g_w16[0 * ROW_U4 + i * 8 + l];
        const uint4 w1 = g_w16[1 * ROW_U4 + i * 8 + l];
        const uint4 w2 = g_w16[2 * ROW_U4 + i * 8 + l];
        float fw0[8], fw1[8], fw2[8];
        h8_to_f8(w0, fw0);
        h8_to_f8(w1, fw1);
        h8_to_f8(w2, fw2);

        float pA[8], pB[8];
        hprod_to_f8(ua[i],  va[i],  pA);
        hprod_to_f8(ub4[i], vb4[i], pB);
#pragma unroll
        for (int j = 0; j < 8; j++) {
            a0 = fmaf(pA[j], fw0[j], a0);
            a1 = fmaf(pA[j], fw1[j], a1);
            a2 = fmaf(pA[j], fw2[j], a2);
            c0 = fmaf(pB[j], fw0[j], c0);
            c1 = fmaf(pB[j], fw1[j], c1);
            c2 = fmaf(pB[j], fw2[j], c2);
        }
    }

    // Butterfly over the 8-lane group: 3 rounds x 6 values (2 quads).
#pragma unroll
    for (int off = 4; off; off >>= 1) {
        a0 += __shfl_xor_sync(0xffffffffu, a0, off);
        a1 += __shfl_xor_sync(0xffffffffu, a1, off);
        a2 += __shfl_xor_sync(0xffffffffu, a2, off);
        c0 += __shfl_xor_sync(0xffffffffu, c0, off);
        c1 += __shfl_xor_sync(0xffffffffu, c1, off);
        c2 += __shfl_xor_sync(0xffffffffu, c2, off);
    }

    if (l < NUM_C) {
        if (val0) {
            float o = fmaf(a0, s0, fmaf(a1, s1, a2 * s2));
            __stcs(out + (size_t)e0 * NUM_C + l, o + ubias0 + vbias0);
        }
        if (val1) {
            float o = fmaf(c0, s0, fmaf(c1, s1, c2 * s2));
            __stcs(out + (size_t)e1 * NUM_C + l, o + ubias1 + vbias1);
        }
    }
}

extern "C" void kernel_launch(void* const* d_in, const int* in_sizes, int n_in,
                              void* d_out, int out_size)
{
    const float* u_feats = (const float*)d_in[0];
    const float* v_feats = (const float*)d_in[1];
    const int*   u_idx   = (const int*)  d_in[2];
    const int*   v_idx   = (const int*)  d_in[3];
    const float* W       = (const float*)d_in[4];
    const float* scalars = (const float*)d_in[5];
    const float* u_bias  = (const float*)d_in[6];
    const float* v_bias  = (const float*)d_in[7];
    float* out = (float*)d_out;

    int E = in_sizes[2];  // u_idx element count

    // Phase 1: convert feature tables + W to fp16 scratch.
    const int n_u = NUM_USERS * ROW_U4;
    const int n_v = NUM_ITEMS * ROW_U4;
    const int n_w = NUM_W * ROW_U4;
    convert_kernel<<<1184, 256>>>(
        reinterpret_cast<const float4*>(u_feats),
        reinterpret_cast<const float4*>(v_feats),
        reinterpret_cast<const float4*>(W),
        n_u, n_v, n_w);

    // Phase 2: main gather kernel.
    int blocks = (E + EDGES_PER_BLOCK - 1) / EDGES_PER_BLOCK;
    bilinear_mixture_kernel<<<blocks, THREADS>>>(
        u_idx, v_idx, scalars, u_bias, v_bias, out, E);
}